// round 4
// baseline (speedup 1.0000x reference)
#include <cuda_runtime.h>

#define NN 100000
#define NE 1250000
#define D  64
#define NB 16

// Scratch (no allocs allowed). Invariant: g_h and g_deg are ZERO at entry of
// every kernel_launch call — zero at module load, and k_transform restores
// them to zero after consuming them. No memsets needed.
__device__ float g_h[(size_t)NN * D];   // sum of x[src] per dst node
__device__ float g_deg[NN];             // in-degree (float)
__device__ float g_Wm[D * D];           // reconstructed W_msg  [i][o]
__device__ float g_Ws[D * D];           // reconstructed W_self [i][o]
__device__ float g_bm[D];
__device__ float g_bs[D];

// ---------------------------------------------------------------------------
// Kernel 1: scatter-add raw x rows (16 threads/edge, float4 vector atomics).
// Block 0 instead reconstructs weights from bases (hides under the scatter).
// ---------------------------------------------------------------------------
__global__ void k_scatter(const float4* __restrict__ x4, const int* __restrict__ ei,
                          const float* __restrict__ bmw, const float* __restrict__ bmb,
                          const float* __restrict__ bsw, const float* __restrict__ bsb,
                          const float* __restrict__ lc) {
    if (blockIdx.x == 0) {
        __shared__ float c[NB];
        if (threadIdx.x < NB) c[threadIdx.x] = lc[threadIdx.x];
        __syncthreads();
        for (int idx = threadIdx.x; idx < D * D; idx += 256) {
            float wm = 0.f, ws = 0.f;
            #pragma unroll
            for (int b = 0; b < NB; b++) {
                wm = fmaf(bmw[idx * NB + b], c[b], wm);
                ws = fmaf(bsw[idx * NB + b], c[b], ws);
            }
            g_Wm[idx] = wm;
            g_Ws[idx] = ws;
        }
        if (threadIdx.x < D) {
            int o = threadIdx.x;
            float bm = 0.f, bs = 0.f;
            #pragma unroll
            for (int b = 0; b < NB; b++) {
                bm = fmaf(bmb[o * NB + b], c[b], bm);
                bs = fmaf(bsb[o * NB + b], c[b], bs);
            }
            g_bm[o] = bm;
            g_bs[o] = bs;
        }
        return;
    }
    unsigned t = (blockIdx.x - 1) * blockDim.x + threadIdx.x;
    unsigned e = t >> 4;
    if (e >= NE) return;
    int j = t & 15;
    int src = __ldg(ei + e);
    int dst = __ldg(ei + NE + e);
    float4 v = __ldg(x4 + (size_t)src * (D / 4) + j);
    float* p = g_h + (size_t)dst * D + j * 4;
    asm volatile("red.global.add.v4.f32 [%0], {%1,%2,%3,%4};"
                 :: "l"(p), "f"(v.x), "f"(v.y), "f"(v.z), "f"(v.w)
                 : "memory");
    if (j == 0) atomicAdd(&g_deg[dst], 1.0f);
}

// ---------------------------------------------------------------------------
// Kernel 2: out = normalize( h @ Wm + x @ Ws + deg*bm + bs )
// 64 nodes x 64 cols per block.  Register-double-buffered 4x4 micro-tile:
// per 4-k step, 8 x LDS.128 feed 64 FFMAs, next fragments prefetched while
// current ones compute.  Also restores g_h/g_deg to zero for the next launch.
// ---------------------------------------------------------------------------
#define IN_STRIDE 132   // 128 + 4 pad
#define W_STRIDE  68    // 64 + 4 pad

__global__ void __launch_bounds__(256, 2)
k_transform(const float* __restrict__ x, float* __restrict__ out) {
    extern __shared__ float smem[];
    float* In   = smem;                      // [64][IN_STRIDE]
    float* Wsh  = In + 64 * IN_STRIDE;       // [128][W_STRIDE]
    float* red  = Wsh + 128 * W_STRIDE;      // [64][17]
    float* nf   = red + 64 * 17;             // [64]
    float* degS = nf + 64;                   // [64]

    int tid = threadIdx.x;
    int n0  = blockIdx.x * 64;

    // Load W (rows 0..63 = Wm, 64..127 = Ws), padded stride
    {
        const float4* wm4 = (const float4*)g_Wm;
        const float4* ws4 = (const float4*)g_Ws;
        for (int i = tid; i < (D * D) / 4; i += 256) {
            int r = i >> 4, c = i & 15;            // r: 0..63, c: 0..15 (float4 units)
            *(float4*)&Wsh[r * W_STRIDE + c * 4]         = wm4[i];
            *(float4*)&Wsh[(r + 64) * W_STRIDE + c * 4]  = ws4[i];
        }
    }
    // Load input tile: In[n][0:64] = h row, In[n][64:128] = x row.
    // Restore g_h to zero as we go.
    {
        const float4* h4 = (const float4*)g_h;
        const float4* x4 = (const float4*)x;
        float4* h4w = (float4*)g_h;
        for (int i = tid; i < 64 * (D / 4); i += 256) {
            int n = i >> 4, j = i & 15;
            int gn = n0 + n;
            float4 hv = make_float4(0.f, 0.f, 0.f, 0.f);
            float4 xv = hv;
            if (gn < NN) {
                size_t off = (size_t)gn * (D / 4) + j;
                hv = h4[off];
                xv = x4[off];
                h4w[off] = make_float4(0.f, 0.f, 0.f, 0.f);
            }
            *(float4*)&In[n * IN_STRIDE + j * 4]      = hv;
            *(float4*)&In[n * IN_STRIDE + 64 + j * 4] = xv;
        }
    }
    // Load degree (and restore to zero)
    if (tid < 64) {
        int gn = n0 + tid;
        float dg = 0.f;
        if (gn < NN) {
            dg = g_deg[gn];
            g_deg[gn] = 0.f;
        }
        degS[tid] = dg;
    }
    __syncthreads();

    int to = tid & 15;   // col group: cols to*4 .. to*4+3
    int tn = tid >> 4;   // node group: nodes tn*4 .. tn*4+3

    const float* aBase = &In[(tn * 4) * IN_STRIDE];   // + r*IN_STRIDE + k
    const float* wBase = &Wsh[to * 4];                // + k*W_STRIDE

    float acc[4][4];
    #pragma unroll
    for (int r = 0; r < 4; r++)
        #pragma unroll
        for (int c = 0; c < 4; c++) acc[r][c] = 0.f;

    float4 aF[2][4], wF[2][4];
    // Prologue: load fragments for k=0
    #pragma unroll
    for (int r = 0; r < 4; r++)
        aF[0][r] = *(const float4*)(aBase + r * IN_STRIDE);
    #pragma unroll
    for (int i = 0; i < 4; i++)
        wF[0][i] = *(const float4*)(wBase + i * W_STRIDE);

    #pragma unroll
    for (int kk = 0; kk < 128; kk += 4) {
        const int cur = (kk >> 2) & 1;
        const int nxt = cur ^ 1;
        if (kk + 4 < 128) {
            #pragma unroll
            for (int r = 0; r < 4; r++)
                aF[nxt][r] = *(const float4*)(aBase + r * IN_STRIDE + kk + 4);
            #pragma unroll
            for (int i = 0; i < 4; i++)
                wF[nxt][i] = *(const float4*)(wBase + (kk + 4 + i) * W_STRIDE);
        }
        #pragma unroll
        for (int r = 0; r < 4; r++) {
            float4 a = aF[cur][r];
            #pragma unroll
            for (int i = 0; i < 4; i++) {
                float av = (i == 0) ? a.x : (i == 1) ? a.y : (i == 2) ? a.z : a.w;
                float4 w = wF[cur][i];
                acc[r][0] = fmaf(av, w.x, acc[r][0]);
                acc[r][1] = fmaf(av, w.y, acc[r][1]);
                acc[r][2] = fmaf(av, w.z, acc[r][2]);
                acc[r][3] = fmaf(av, w.w, acc[r][3]);
            }
        }
    }

    // Epilogue: bias + deg*b_msg, per-node L2 norm, normalized store.
    float bmv[4], bsv[4];
    #pragma unroll
    for (int c = 0; c < 4; c++) {
        bmv[c] = g_bm[to * 4 + c];
        bsv[c] = g_bs[to * 4 + c];
    }

    float vals[4][4];
    #pragma unroll
    for (int r = 0; r < 4; r++) {
        float dg = degS[tn * 4 + r];
        float ss = 0.f;
        #pragma unroll
        for (int c = 0; c < 4; c++) {
            float v = acc[r][c] + dg * bmv[c] + bsv[c];
            vals[r][c] = v;
            ss = fmaf(v, v, ss);
        }
        red[(tn * 4 + r) * 17 + to] = ss;
    }
    __syncthreads();

    if (tid < 64) {
        float s = 0.f;
        #pragma unroll
        for (int t2 = 0; t2 < 16; t2++) s += red[tid * 17 + t2];
        float nrm = sqrtf(s);
        nf[tid] = 1.f / fmaxf(nrm, 1e-12f);
    }
    __syncthreads();

    #pragma unroll
    for (int r = 0; r < 4; r++) {
        int gn = n0 + tn * 4 + r;
        if (gn < NN) {
            float f = nf[tn * 4 + r];
            float4 o4 = make_float4(vals[r][0] * f, vals[r][1] * f,
                                    vals[r][2] * f, vals[r][3] * f);
            *(float4*)&out[(size_t)gn * D + to * 4] = o4;
        }
    }
}

#define SMEM_BYTES ((64 * IN_STRIDE + 128 * W_STRIDE + 64 * 17 + 64 + 64) * (int)sizeof(float))

extern "C" void kernel_launch(void* const* d_in, const int* in_sizes, int n_in,
                              void* d_out, int out_size) {
    const float* x   = (const float*)d_in[0];
    const int*   ei  = (const int*)d_in[1];
    const float* bmw = (const float*)d_in[2];
    const float* bmb = (const float*)d_in[3];
    const float* bsw = (const float*)d_in[4];
    const float* bsb = (const float*)d_in[5];
    const float* lc  = (const float*)d_in[6];
    float* out = (float*)d_out;

    unsigned total = (unsigned)NE * 16u;
    unsigned nblk = 1u + (total + 255u) / 256u;
    k_scatter<<<nblk, 256>>>((const float4*)x, ei, bmw, bmb, bsw, bsb, lc);

    cudaFuncSetAttribute(k_transform, cudaFuncAttributeMaxDynamicSharedMemorySize, SMEM_BYTES);
    k_transform<<<(NN + 63) / 64, 256, SMEM_BYTES>>>(x, out);
}

// round 5
// speedup vs baseline: 1.3175x; 1.3175x over previous
#include <cuda_runtime.h>

#define NN 100000
#define NE 1250000
#define D  64
#define NB 16

// Scratch (no allocs allowed) — zeroed every launch via cudaMemsetAsync.
__device__ float g_h[(size_t)NN * D];   // sum of x[src] per dst node
__device__ float g_deg[NN];             // in-degree (float)
__device__ float g_Wm[D * D];           // reconstructed W_msg  [i][o]
__device__ float g_Ws[D * D];           // reconstructed W_self [i][o]
__device__ float g_bm[D];
__device__ float g_bs[D];

// ---------------------------------------------------------------------------
// Kernel 1: reconstruct weights from bases (tiny)
// ---------------------------------------------------------------------------
__global__ void k_weights(const float* __restrict__ bmw, const float* __restrict__ bmb,
                          const float* __restrict__ bsw, const float* __restrict__ bsb,
                          const float* __restrict__ lc) {
    __shared__ float c[NB];
    if (threadIdx.x < NB) c[threadIdx.x] = lc[threadIdx.x];
    __syncthreads();
    int idx = blockIdx.x * blockDim.x + threadIdx.x;
    if (idx < D * D) {
        float wm = 0.f, ws = 0.f;
        #pragma unroll
        for (int b = 0; b < NB; b++) {
            wm = fmaf(bmw[idx * NB + b], c[b], wm);
            ws = fmaf(bsw[idx * NB + b], c[b], ws);
        }
        g_Wm[idx] = wm;
        g_Ws[idx] = ws;
    } else if (idx < D * D + D) {
        int o = idx - D * D;
        float bm = 0.f, bs = 0.f;
        #pragma unroll
        for (int b = 0; b < NB; b++) {
            bm = fmaf(bmb[o * NB + b], c[b], bm);
            bs = fmaf(bsb[o * NB + b], c[b], bs);
        }
        g_bm[o] = bm;
        g_bs[o] = bs;
    }
}

// ---------------------------------------------------------------------------
// Kernel 2: scatter-add raw x rows (16 threads/edge, float4 vector atomics).
// ---------------------------------------------------------------------------
__global__ void k_scatter(const float4* __restrict__ x4, const int* __restrict__ ei) {
    unsigned t = blockIdx.x * blockDim.x + threadIdx.x;
    unsigned e = t >> 4;
    if (e >= NE) return;
    int j = t & 15;
    int src = __ldg(ei + e);
    int dst = __ldg(ei + NE + e);
    float4 v = __ldg(x4 + (size_t)src * (D / 4) + j);
    float* p = g_h + (size_t)dst * D + j * 4;
    asm volatile("red.global.add.v4.f32 [%0], {%1,%2,%3,%4};"
                 :: "l"(p), "f"(v.x), "f"(v.y), "f"(v.z), "f"(v.w)
                 : "memory");
    if (j == 0) atomicAdd(&g_deg[dst], 1.0f);
}

// ---------------------------------------------------------------------------
// Kernel 3: out = normalize( h @ Wm + x @ Ws + deg*bm + bs )
// Tensor-core path: mma.sync.m16n8k8 tf32 with 3xTF32 splitting for fp32-level
// accuracy.  Block = 64 nodes x 64 cols, 128 threads (4 warps); each warp
// computes 16 rows x 64 cols (8 n-tiles), K = 128 (concat [h|x]).
// ---------------------------------------------------------------------------
#define IN_STRIDE 132   // 128 + 4 pad  (A loads bank-conflict-free)
#define W_STRIDE  72    // 64 + 8 pad   (B loads bank-conflict-free)

__device__ __forceinline__ unsigned f2tf(float v) {
    unsigned r;
    asm("cvt.rna.tf32.f32 %0, %1;" : "=r"(r) : "f"(v));
    return r;
}

#define MMA_TF32(c0,c1,c2,c3, a0,a1,a2,a3, b0,b1)                               \
    asm volatile("mma.sync.aligned.m16n8k8.row.col.f32.tf32.tf32.f32 "          \
                 "{%0,%1,%2,%3}, {%4,%5,%6,%7}, {%8,%9}, {%0,%1,%2,%3};"        \
                 : "+f"(c0), "+f"(c1), "+f"(c2), "+f"(c3)                       \
                 : "r"(a0), "r"(a1), "r"(a2), "r"(a3), "r"(b0), "r"(b1))

__global__ void __launch_bounds__(128)
k_transform(const float* __restrict__ x, float* __restrict__ out) {
    extern __shared__ float smem[];
    float* In   = smem;                     // [64][IN_STRIDE]  concat(h|x)
    float* Wsh  = In + 64 * IN_STRIDE;      // [128][W_STRIDE]  k-major weights
    float* degS = Wsh + 128 * W_STRIDE;     // [64]
    float* bmS  = degS + 64;                // [64]
    float* bsS  = bmS + 64;                 // [64]

    int tid  = threadIdx.x;
    int w    = tid >> 5;        // warp 0..3 -> rows w*16 .. w*16+15
    int lane = tid & 31;
    int g    = lane >> 2;       // 0..7
    int t    = lane & 3;        // 0..3
    int n0   = blockIdx.x * 64;

    // --- Prologue: stage W and inputs into shared ---
    {
        const float4* wm4 = (const float4*)g_Wm;
        const float4* ws4 = (const float4*)g_Ws;
        for (int i = tid; i < (D * D) / 4; i += 128) {
            int r = i >> 4, c = i & 15;
            *(float4*)&Wsh[r * W_STRIDE + c * 4]        = wm4[i];
            *(float4*)&Wsh[(r + 64) * W_STRIDE + c * 4] = ws4[i];
        }
    }
    {
        const float4* h4 = (const float4*)g_h;
        const float4* x4 = (const float4*)x;
        for (int i = tid; i < 64 * (D / 4); i += 128) {
            int n = i >> 4, j = i & 15;
            int gn = n0 + n;
            float4 hv = make_float4(0.f, 0.f, 0.f, 0.f);
            float4 xv = hv;
            if (gn < NN) {
                size_t off = (size_t)gn * (D / 4) + j;
                hv = h4[off];
                xv = x4[off];
            }
            *(float4*)&In[n * IN_STRIDE + j * 4]      = hv;
            *(float4*)&In[n * IN_STRIDE + 64 + j * 4] = xv;
        }
    }
    if (tid < 64) {
        int gn = n0 + tid;
        degS[tid] = (gn < NN) ? g_deg[gn] : 0.f;
        bmS[tid]  = g_bm[tid];
        bsS[tid]  = g_bs[tid];
    }
    __syncthreads();

    // --- Main loop: 16 k-chunks of 8, 8 n-tiles, 3xTF32 per tile ---
    float acc[8][4];
    #pragma unroll
    for (int tl = 0; tl < 8; tl++)
        #pragma unroll
        for (int j = 0; j < 4; j++) acc[tl][j] = 0.f;

    const int rowA = w * 16 + g;
    const float* aRow0 = &In[rowA * IN_STRIDE];
    const float* aRow1 = &In[(rowA + 8) * IN_STRIDE];

    #pragma unroll 4
    for (int kc = 0; kc < 16; kc++) {
        int kb = kc * 8;
        // A fragment: a0=A[g][t], a1=A[g+8][t], a2=A[g][t+4], a3=A[g+8][t+4]
        float fa0 = aRow0[kb + t];
        float fa1 = aRow1[kb + t];
        float fa2 = aRow0[kb + t + 4];
        float fa3 = aRow1[kb + t + 4];
        unsigned aH0 = f2tf(fa0), aH1 = f2tf(fa1), aH2 = f2tf(fa2), aH3 = f2tf(fa3);
        unsigned aL0 = f2tf(fa0 - __uint_as_float(aH0));
        unsigned aL1 = f2tf(fa1 - __uint_as_float(aH1));
        unsigned aL2 = f2tf(fa2 - __uint_as_float(aH2));
        unsigned aL3 = f2tf(fa3 - __uint_as_float(aH3));

        const float* wb0 = &Wsh[(kb + t) * W_STRIDE + g];
        const float* wb1 = &Wsh[(kb + t + 4) * W_STRIDE + g];
        #pragma unroll
        for (int tl = 0; tl < 8; tl++) {
            // B fragment (KxN, col operand): b0=B[t][g], b1=B[t+4][g]
            float fb0 = wb0[tl * 8];
            float fb1 = wb1[tl * 8];
            unsigned bH0 = f2tf(fb0), bH1 = f2tf(fb1);
            unsigned bL0 = f2tf(fb0 - __uint_as_float(bH0));
            unsigned bL1 = f2tf(fb1 - __uint_as_float(bH1));
            MMA_TF32(acc[tl][0], acc[tl][1], acc[tl][2], acc[tl][3],
                     aH0, aH1, aH2, aH3, bH0, bH1);
            MMA_TF32(acc[tl][0], acc[tl][1], acc[tl][2], acc[tl][3],
                     aH0, aH1, aH2, aH3, bL0, bL1);
            MMA_TF32(acc[tl][0], acc[tl][1], acc[tl][2], acc[tl][3],
                     aL0, aL1, aL2, aL3, bH0, bH1);
        }
    }

    // --- Epilogue: bias + deg*bm, L2 norm across quad lanes, store ---
    // Lane holds rows r0=rowA, r1=rowA+8; cols (8*tl + 2t, +1).
    float dg0 = degS[rowA];
    float dg1 = degS[rowA + 8];
    float ss0 = 0.f, ss1 = 0.f;
    #pragma unroll
    for (int tl = 0; tl < 8; tl++) {
        int c0 = tl * 8 + 2 * t;
        float bm0 = bmS[c0], bm1 = bmS[c0 + 1];
        float bs0 = bsS[c0], bs1 = bsS[c0 + 1];
        float v00 = acc[tl][0] + dg0 * bm0 + bs0;   // row r0, col c0
        float v01 = acc[tl][1] + dg0 * bm1 + bs1;   // row r0, col c0+1
        float v10 = acc[tl][2] + dg1 * bm0 + bs0;   // row r1, col c0
        float v11 = acc[tl][3] + dg1 * bm1 + bs1;   // row r1, col c0+1
        acc[tl][0] = v00; acc[tl][1] = v01; acc[tl][2] = v10; acc[tl][3] = v11;
        ss0 = fmaf(v00, v00, fmaf(v01, v01, ss0));
        ss1 = fmaf(v10, v10, fmaf(v11, v11, ss1));
    }
    // reduce over the 4 lanes of the quad (same g, t = 0..3)
    ss0 += __shfl_xor_sync(0xffffffffu, ss0, 1);
    ss0 += __shfl_xor_sync(0xffffffffu, ss0, 2);
    ss1 += __shfl_xor_sync(0xffffffffu, ss1, 1);
    ss1 += __shfl_xor_sync(0xffffffffu, ss1, 2);
    float f0 = 1.f / fmaxf(sqrtf(ss0), 1e-12f);
    float f1 = 1.f / fmaxf(sqrtf(ss1), 1e-12f);

    int gn0 = n0 + rowA;
    int gn1 = gn0 + 8;
    #pragma unroll
    for (int tl = 0; tl < 8; tl++) {
        int c0 = tl * 8 + 2 * t;
        if (gn0 < NN)
            *(float2*)&out[(size_t)gn0 * D + c0] = make_float2(acc[tl][0] * f0, acc[tl][1] * f0);
        if (gn1 < NN)
            *(float2*)&out[(size_t)gn1 * D + c0] = make_float2(acc[tl][2] * f1, acc[tl][3] * f1);
    }
}

#define SMEM_BYTES ((64 * IN_STRIDE + 128 * W_STRIDE + 64 * 3) * (int)sizeof(float))

extern "C" void kernel_launch(void* const* d_in, const int* in_sizes, int n_in,
                              void* d_out, int out_size) {
    const float* x   = (const float*)d_in[0];
    const int*   ei  = (const int*)d_in[1];
    const float* bmw = (const float*)d_in[2];
    const float* bmb = (const float*)d_in[3];
    const float* bsw = (const float*)d_in[4];
    const float* bsb = (const float*)d_in[5];
    const float* lc  = (const float*)d_in[6];
    float* out = (float*)d_out;

    void* hptr = nullptr;
    void* dptr = nullptr;
    cudaGetSymbolAddress(&hptr, g_h);
    cudaGetSymbolAddress(&dptr, g_deg);
    cudaMemsetAsync(hptr, 0, sizeof(float) * (size_t)NN * D);
    cudaMemsetAsync(dptr, 0, sizeof(float) * NN);

    k_weights<<<(D * D + D + 255) / 256, 256>>>(bmw, bmb, bsw, bsb, lc);

    unsigned total = (unsigned)NE * 16u;
    k_scatter<<<(total + 255) / 256, 256>>>((const float4*)x, ei);

    cudaFuncSetAttribute(k_transform, cudaFuncAttributeMaxDynamicSharedMemorySize, SMEM_BYTES);
    k_transform<<<(NN + 63) / 64, 128, SMEM_BYTES>>>(x, out);
}